// round 1
// baseline (speedup 1.0000x reference)
#include <cuda_runtime.h>

// QPSK modulator: bits (256,16384) int32 -> Gray QPSK symbols -> x16 zero-stuff
// (offset 8) -> RRC filter (K=128) -> out (256, 131072, 2) float32.
//
// Polyphase identity: y[16q+p] = sum_{i=0..7} sym[q+jmin+i] * rrc[k0+16i],
//   k0 = (71-p)&15, jmin = (p<=7) ? -4 : -3, then scaled by sqrt(16).
// Symbols are (+-1/sqrt2, +-1/sqrt2); we fold sqrt(16)/sqrt(2)=2*sqrt(2) into
// the taps so shared symbols are just +-1.

#define B_ROWS     256
#define NUM_BITS   16384
#define NS         8192           // symbols per row
#define SPS        16
#define UP_LEN     (NS * SPS)     // 131072
#define K_TAPS     128

#define SYMS_PER_BLOCK   128      // -> 2048 outputs per block
#define OUTS_PER_BLOCK   (SYMS_PER_BLOCK * SPS)
#define THREADS          256
#define HALO_L           4
#define SYM_TILE         (SYMS_PER_BLOCK + 8)   // [q0-4, q0+131] = 136 symbols

__global__ __launch_bounds__(THREADS)
void qpsk_mod_kernel(const int* __restrict__ bits,
                     const float* __restrict__ rrc,
                     float4* __restrict__ out4)   // out viewed as float4 (2 complex outputs)
{
    __shared__ float  s_rrc[K_TAPS];
    __shared__ float2 s_sym[SYM_TILE];

    const int tid  = threadIdx.x;
    const int tile = blockIdx.x;          // 0..63
    const int row  = blockIdx.y;          // 0..255
    const int q0   = tile * SYMS_PER_BLOCK;

    // Stage taps, pre-scaled by sqrt(SPS)/sqrt(2) = 2*sqrt(2)
    if (tid < K_TAPS)
        s_rrc[tid] = rrc[tid] * 2.82842712474619f;

    // Stage symbols with halo; zero outside [0, NS)
    const int2* bits2 = (const int2*)(bits + (long long)row * NUM_BITS);
    for (int s = tid; s < SYM_TILE; s += THREADS) {
        int g = q0 - HALO_L + s;
        float re = 0.f, im = 0.f;
        if (g >= 0 && g < NS) {
            int2 bb = bits2[g];           // bb.x = bits[2g] (-> imag), bb.y = bits[2g+1] (-> real)
            re = bb.y ? -1.f : 1.f;
            im = bb.x ? -1.f : 1.f;
        }
        s_sym[s] = make_float2(re, im);
    }
    __syncthreads();

    // Each thread computes 4 pairs of outputs (8 outputs), float4 stores.
    // pair index pi in [0, 1024); local output n = 2*pi, 2*pi+1.
    const long long out_pair_base = ((long long)row * UP_LEN + (long long)tile * OUTS_PER_BLOCK) >> 1;

    #pragma unroll
    for (int it = 0; it < 4; it++) {
        int pi = it * THREADS + tid;      // 0..1023
        int n0 = 2 * pi;                  // even local output
        float acc[4] = {0.f, 0.f, 0.f, 0.f};   // re0, im0, re1, im1

        #pragma unroll
        for (int d = 0; d < 2; d++) {
            int n  = n0 + d;
            int p  = n & 15;
            int k0 = (71 - p) & 15;
            // shared symbol base = q_local + 4 + jmin  (jmin = -4 for p<=7, -3 for p>=8)
            int sbase = (n >> 4) + ((p >= 8) ? 1 : 0);
            float are = 0.f, aim = 0.f;
            #pragma unroll
            for (int i = 0; i < 8; i++) {
                float  t = s_rrc[k0 + 16 * i];
                float2 s = s_sym[sbase + i];
                are = fmaf(t, s.x, are);
                aim = fmaf(t, s.y, aim);
            }
            acc[2 * d + 0] = are;
            acc[2 * d + 1] = aim;
        }

        out4[out_pair_base + pi] = make_float4(acc[0], acc[1], acc[2], acc[3]);
    }
}

extern "C" void kernel_launch(void* const* d_in, const int* in_sizes, int n_in,
                              void* d_out, int out_size)
{
    const int*   bits = (const int*)d_in[0];
    const float* rrc  = (const float*)d_in[1];
    float4*      out  = (float4*)d_out;

    dim3 grid(UP_LEN / OUTS_PER_BLOCK, B_ROWS);   // (64, 256)
    qpsk_mod_kernel<<<grid, THREADS>>>(bits, rrc, out);
}

// round 2
// speedup vs baseline: 1.3015x; 1.3015x over previous
#include <cuda_runtime.h>

// QPSK modulator: bits (256,16384) int32 -> Gray QPSK -> x16 zero-stuff
// (offset 8) -> RRC (K=128) -> out (256, 131072, 2) float32.
//
// Polyphase: y[16q+p] = sum_{i=0..7} sym[q+jmin+i] * rrc[k0+16i],
//   k0 = (71-p)&15, jmin = (p<=7) ? -4 : -3, scaled by sqrt(16).
// sqrt(16)/sqrt(2) folded into taps so symbols are +-1.
//
// R2: each thread owns a FIXED even/odd phase pair -> its 16 taps live in
// registers (duplicated as (t,t) for fma.rn.f32x2). Inner loop: 8 LDS.64
// (symbols, shared by both phases) + 16 FFMA2 + 1 STG.128.

#define B_ROWS     256
#define NUM_BITS   16384
#define NS         8192
#define SPS        16
#define UP_LEN     (NS * SPS)
#define K_TAPS     128

#define SYMS_PER_BLOCK   128
#define OUTS_PER_BLOCK   (SYMS_PER_BLOCK * SPS)
#define THREADS          256
#define HALO_L           4
#define SYM_TILE         (SYMS_PER_BLOCK + 8)

typedef unsigned long long ull;

__device__ __forceinline__ ull pack2(float lo, float hi) {
    ull v;
    asm("mov.b64 %0, {%1, %2};" : "=l"(v) : "f"(lo), "f"(hi));
    return v;
}

__device__ __forceinline__ void fma2(ull& acc, ull a, ull b) {
    asm("fma.rn.f32x2 %0, %1, %2, %0;" : "+l"(acc) : "l"(a), "l"(b));
}

__global__ __launch_bounds__(THREADS)
void qpsk_mod_kernel(const int* __restrict__ bits,
                     const float* __restrict__ rrc,
                     ulonglong2* __restrict__ out4)
{
    __shared__ float s_rrc[K_TAPS];
    __shared__ float2 s_sym[SYM_TILE];

    const int tid  = threadIdx.x;
    const int tile = blockIdx.x;          // 0..63
    const int row  = blockIdx.y;          // 0..255
    const int q0   = tile * SYMS_PER_BLOCK;

    // Stage taps, pre-scaled by sqrt(SPS)/sqrt(2) = 2*sqrt(2)
    if (tid < K_TAPS)
        s_rrc[tid] = rrc[tid] * 2.82842712474619f;

    // Stage symbols (+-1) with halo; zero outside [0, NS)
    const int2* bits2 = (const int2*)(bits + (long long)row * NUM_BITS);
    for (int s = tid; s < SYM_TILE; s += THREADS) {
        int g = q0 - HALO_L + s;
        float re = 0.f, im = 0.f;
        if (g >= 0 && g < NS) {
            int2 bb = bits2[g];   // bb.x = bits[2g] (-> imag), bb.y = bits[2g+1] (-> real)
            re = bb.y ? -1.f : 1.f;
            im = bb.x ? -1.f : 1.f;
        }
        s_sym[s] = make_float2(re, im);
    }
    __syncthreads();

    // This thread's fixed phases: p0 (even) and p0+1.
    const int p0   = (2 * tid) & 15;
    const int flag = (p0 >= 8) ? 1 : 0;       // sbase adjustment, same for both phases
    const int k0e  = (71 - p0) & 15;          // odd
    const int k0o  = k0e - 1;                 // taps for phase p0+1 (even index)

    // Taps -> registers, duplicated for f32x2.
    ull te2[8], to2[8];
    #pragma unroll
    for (int i = 0; i < 8; i++) {
        float te = s_rrc[k0e + 16 * i];
        float to = s_rrc[k0o + 16 * i];
        te2[i] = pack2(te, te);
        to2[i] = pack2(to, to);
    }

    const ull* s_sym64 = (const ull*)s_sym;
    const long long out_pair_base =
        ((long long)row * UP_LEN + (long long)tile * OUTS_PER_BLOCK) >> 1;

    #pragma unroll
    for (int it = 0; it < 4; it++) {
        const int pi    = it * THREADS + tid;          // 0..1023
        const int sbase = it * 32 + (tid >> 3) + flag; // shared symbol window start

        ull acc_e = 0ULL;   // (re, im) for even phase
        ull acc_o = 0ULL;   // (re, im) for odd phase
        #pragma unroll
        for (int i = 0; i < 8; i++) {
            ull s2 = s_sym64[sbase + i];
            fma2(acc_e, te2[i], s2);
            fma2(acc_o, to2[i], s2);
        }

        ulonglong2 o;
        o.x = acc_e;   // (re[n0], im[n0])
        o.y = acc_o;   // (re[n0+1], im[n0+1])
        out4[out_pair_base + pi] = o;
    }
}

extern "C" void kernel_launch(void* const* d_in, const int* in_sizes, int n_in,
                              void* d_out, int out_size)
{
    const int*   bits = (const int*)d_in[0];
    const float* rrc  = (const float*)d_in[1];
    ulonglong2*  out  = (ulonglong2*)d_out;

    dim3 grid(UP_LEN / OUTS_PER_BLOCK, B_ROWS);   // (64, 256)
    qpsk_mod_kernel<<<grid, THREADS>>>(bits, rrc, out);
}